// round 11
// baseline (speedup 1.0000x reference)
#include <cuda_runtime.h>
#include <cuda_bf16.h>
#include <cuda_fp8.h>
#include <cuda_fp16.h>
#include <math.h>
#include <float.h>
#include <stdint.h>

#define NROWS 8192
#define DIM 128
#define N_TILES 64
#define NCTA 296                    // exactly one resident wave (2 CTAs/SM x 148)
#define EPSL 1e-8f

// fp8 tile: 128 rows x 128 bytes, padded to 144B rows (conflict-free ldmatrix)
#define AS 144
#define TILE_SM (128 * AS)          // 18432
#define OFF_A0 0
#define OFF_A1 TILE_SM
#define OFF_B0 (2 * TILE_SM)
#define OFF_B1 (3 * TILE_SM)
#define SMEM_BYTES (4 * TILE_SM)    // 73728 -> 2 CTAs/SM = 147456 <= 227KB

__device__ __align__(16) uint32_t g_f8[NROWS * DIM / 4];  // e4m3(e*sqrt2)
__device__ __align__(16) float g_M[NROWS];     // row softmax reference 2*|e_i|^2
__device__ __align__(16) float g_Mpmin[N_TILES * 8];  // per-tile per-pattern min M
__device__ float g_p[NROWS];
__device__ float g_n[NROWS];
__device__ int   g_sync;            // phase-0 barrier (reset by finalizer)
__device__ int   g_done;            // finalize ticket (reset by finalizer)

// ---------------- helpers (baseline PTX, valid on sm_103 target) ----------------
__device__ __forceinline__ uint32_t smem_u32(const void* p) {
    uint32_t a;
    asm("{ .reg .u64 t; cvta.to.shared.u64 t, %1; cvt.u32.u64 %0, t; }" : "=r"(a) : "l"(p));
    return a;
}
__device__ __forceinline__ void cpa16(uint32_t dst, const void* src) {
    asm volatile("cp.async.cg.shared.global [%0], [%1], 16;" :: "r"(dst), "l"(src));
}
__device__ __forceinline__ void ldsm4(uint32_t* r, uint32_t a) {
    asm volatile("ldmatrix.sync.aligned.m8n8.x4.shared.b16 {%0,%1,%2,%3}, [%4];"
                 : "=r"(r[0]), "=r"(r[1]), "=r"(r[2]), "=r"(r[3]) : "r"(a));
}
__device__ __forceinline__ void mma16832h(uint32_t* c, const uint32_t* a, const uint32_t* b) {
    asm volatile("mma.sync.aligned.m16n8k32.row.col.f16.e4m3.e4m3.f16 "
                 "{%0,%1}, {%2,%3,%4,%5}, {%6,%7}, {%0,%1};"
                 : "+r"(c[0]), "+r"(c[1])
                 : "r"(a[0]), "r"(a[1]), "r"(a[2]), "r"(a[3]), "r"(b[0]), "r"(b[1]));
}
__device__ __forceinline__ void mma16832h_z(uint32_t* c, const uint32_t* a, const uint32_t* b) {
    asm volatile("mma.sync.aligned.m16n8k32.row.col.f16.e4m3.e4m3.f16 "
                 "{%0,%1}, {%2,%3,%4,%5}, {%6,%7}, {%8,%8};"
                 : "=r"(c[0]), "=r"(c[1])
                 : "r"(a[0]), "r"(a[1]), "r"(a[2]), "r"(a[3]), "r"(b[0]), "r"(b[1]), "r"(0u));
}
__device__ __forceinline__ void copy_tile(uint32_t dstBase, const void* src, int tid) {
    #pragma unroll
    for (int jj = 0; jj < 4; ++jj) {
        int c = jj * 256 + tid;
        int row = c >> 3, col = c & 7;
        cpa16(dstBase + row * AS + col * 16, (const char*)src + row * 128 + col * 16);
    }
}

// ================= single fused persistent kernel =================
__global__ __launch_bounds__(256, 2)
void fused_kernel(const int* __restrict__ labels, const float* __restrict__ emb,
                  float* __restrict__ out) {
    extern __shared__ unsigned char smem[];
    const uint32_t sb = smem_u32(smem);
    const int tid = threadIdx.x, lane = tid & 31, wid = tid >> 5;
    const int b = blockIdx.x;

    // -------- phase 0: CTAs 0..63 convert one 128-row tile each --------
    if (b < N_TILES) {
        float* Msm = (float*)smem;                 // 128 floats
        const float4* e4 = (const float4*)emb;
        const float s = 1.41421356237f;            // folds 1/TEMPERATURE
        #pragma unroll
        for (int rr = 0; rr < 16; ++rr) {
            const int rl = wid * 16 + rr;
            const int row = b * 128 + rl;
            float4 v = e4[row * 32 + lane];
            unsigned b0 = __nv_cvt_float_to_fp8(v.x * s, __NV_SATFINITE, __NV_E4M3);
            unsigned b1 = __nv_cvt_float_to_fp8(v.y * s, __NV_SATFINITE, __NV_E4M3);
            unsigned b2 = __nv_cvt_float_to_fp8(v.z * s, __NV_SATFINITE, __NV_E4M3);
            unsigned b3 = __nv_cvt_float_to_fp8(v.w * s, __NV_SATFINITE, __NV_E4M3);
            g_f8[row * 32 + lane] = b0 | (b1 << 8) | (b2 << 16) | (b3 << 24);
            float nr = v.x * v.x + v.y * v.y + v.z * v.z + v.w * v.w;
            #pragma unroll
            for (int o = 16; o; o >>= 1) nr += __shfl_xor_sync(0xffffffffu, nr, o);
            if (lane == 0) {
                float M = 2.f * nr;
                Msm[rl] = M;
                g_M[row] = M;
                g_p[row] = 0.f;
                g_n[row] = 0.f;
            }
        }
        __syncthreads();
        if (tid < 8) {                             // pattern (wn, q) minima
            const int wn = tid >> 2, q = tid & 3;
            float m = FLT_MAX;
            #pragma unroll
            for (int nt = 0; nt < 8; ++nt) {
                m = fminf(m, Msm[wn * 64 + nt * 8 + q * 2]);
                m = fminf(m, Msm[wn * 64 + nt * 8 + q * 2 + 1]);
            }
            g_Mpmin[b * 8 + tid] = m;
        }
    }

    // -------- grid barrier (all 296 CTAs co-resident: single wave) --------
    __syncthreads();
    if (tid == 0) {
        __threadfence();
        atomicAdd(&g_sync, 1);
        while (*(volatile int*)&g_sync < NCTA) __nanosleep(128);
    }
    __syncthreads();
    __threadfence();

    // -------- phase 1: triangular jobs --------
    const int warp_m = wid & 3, warp_n = wid >> 2;       // 4 x 2 warp grid
    const int g0 = b * 7 + (b < 8 ? b : 8);              // 2080 = 296*7 + 8
    const int njobs = 7 + (b < 8 ? 1 : 0);

    int ti = 0, rem = g0;
    while (rem >= N_TILES - ti) { rem -= N_TILES - ti; ++ti; }
    int tj = ti + rem;

    int curA = -1, aBuf = 0;
    int rowG[4], myLab[4];
    float Mref[4];
    uint32_t af[2][4][4];

    copy_tile(sb + OFF_A0, (const char*)g_f8 + ti * 128 * DIM, tid);
    copy_tile(sb + OFF_B0, (const char*)g_f8 + tj * 128 * DIM, tid);
    asm volatile("cp.async.commit_group;");

    for (int k = 0; k < njobs; ++k) {
        const int buf = k & 1, nbuf = buf ^ 1;

        asm volatile("cp.async.wait_group 0;");
        __syncthreads();                                 // job k data visible

        const float minM = g_Mpmin[tj * 8 + warp_n * 4 + (lane & 3)];  // early LDG

        if (ti != curA) {                                // A fragments + row info
            curA = ti;
            const uint32_t abase = sb + (aBuf ? OFF_A1 : OFF_A0);
            const int arow = warp_m * 32 + (lane & 15);
            #pragma unroll
            for (int mt = 0; mt < 2; ++mt)
                #pragma unroll
                for (int ks = 0; ks < 4; ++ks)
                    ldsm4(af[mt][ks], abase + (arow + mt * 16) * AS + ks * 32 + (lane >> 4) * 16);
            #pragma unroll
            for (int s = 0; s < 4; ++s) {
                rowG[s]  = ti * 128 + warp_m * 32 + (s >> 1) * 16 + (s & 1) * 8 + (lane >> 2);
                myLab[s] = labels[rowG[s]];
                Mref[s]  = g_M[rowG[s]];
            }
        }

        // prefetch job k+1 (B always; A only on tile change, into the idle slot)
        int ni = ti, nj = tj + 1;
        if (nj == N_TILES) { ni = ti + 1; nj = ni; }
        if (k + 1 < njobs) {
            copy_tile(sb + (nbuf ? OFF_B1 : OFF_B0), (const char*)g_f8 + nj * 128 * DIM, tid);
            if (ni != ti) {
                aBuf ^= 1;
                copy_tile(sb + (aBuf ? OFF_A1 : OFF_A0), (const char*)g_f8 + ni * 128 * DIM, tid);
            }
        }
        asm volatile("cp.async.commit_group;");

        // ---- GEMM: 32x64 per warp, f16 accumulators ----
        uint32_t acc[2][8][2];
        const uint32_t bbase = sb + (buf ? OFF_B1 : OFF_B0);
        #pragma unroll
        for (int ks = 0; ks < 4; ++ks) {
            uint32_t bfr[8][2];
            #pragma unroll
            for (int np = 0; np < 4; ++np) {
                uint32_t r[4];
                uint32_t addr = bbase
                    + (warp_n * 64 + np * 16 + ((lane >> 4) & 1) * 8 + (lane & 7)) * AS
                    + ks * 32 + ((lane >> 3) & 1) * 16;
                ldsm4(r, addr);
                bfr[np * 2][0] = r[0]; bfr[np * 2][1] = r[1];
                bfr[np * 2 + 1][0] = r[2]; bfr[np * 2 + 1][1] = r[3];
            }
            #pragma unroll
            for (int mt = 0; mt < 2; ++mt)
                #pragma unroll
                for (int nt = 0; nt < 8; ++nt) {
                    if (ks == 0) mma16832h_z(acc[mt][nt], af[mt][0], bfr[nt]);
                    else         mma16832h(acc[mt][nt], af[mt][ks], bfr[nt]);
                }
        }

        const int colBase = tj * 128;

        // ---- row-side epilogue: packed-half max scan + rare slow path ----
        float smaxf[4];
        float ps[4] = {0.f,0.f,0.f,0.f}, ns[4] = {0.f,0.f,0.f,0.f};
        #pragma unroll
        for (int s = 0; s < 4; ++s) {
            const int mt = s >> 1, rh = s & 1;
            __half2 m2 = *(const __half2*)&acc[mt][0][rh];
            #pragma unroll
            for (int nt = 1; nt < 8; ++nt)
                m2 = __hmax2(m2, *(const __half2*)&acc[mt][nt][rh]);
            smaxf[s] = __half2float(__hmax(__low2half(m2), __high2half(m2)));
            if (smaxf[s] > Mref[s] - 87.f) {             // rare (diagonal tiles)
                const int rg = rowG[s], li = myLab[s];
                #pragma unroll
                for (int nt = 0; nt < 8; ++nt) {
                    float2 f2 = __half22float2(*(const __half2*)&acc[mt][nt][rh]);
                    #pragma unroll
                    for (int c = 0; c < 2; ++c) {
                        float x = (c ? f2.y : f2.x) - Mref[s];
                        if (x > -87.f) {
                            int ci = warp_n * 64 + nt * 8 + (lane & 3) * 2 + c;
                            if (colBase + ci != rg) {
                                float e = __expf(x);
                                int lj = labels[colBase + ci];   // L2-hot
                                bool pos = (li == 0) | (lj == li) | (lj == 0);
                                if (pos) ps[s] += e; else ns[s] += e;
                            }
                        }
                    }
                }
            }
        }
        float any = ps[0]+ps[1]+ps[2]+ps[3]+ns[0]+ns[1]+ns[2]+ns[3];
        if (__any_sync(0xffffffffu, any != 0.f)) {
            #pragma unroll
            for (int s = 0; s < 4; ++s) {
                ps[s] += __shfl_xor_sync(0xffffffffu, ps[s], 1);
                ps[s] += __shfl_xor_sync(0xffffffffu, ps[s], 2);
                ns[s] += __shfl_xor_sync(0xffffffffu, ns[s], 1);
                ns[s] += __shfl_xor_sync(0xffffffffu, ns[s], 2);
                if ((lane & 3) == 0) {
                    if (ps[s] != 0.f) atomicAdd(&g_p[rowG[s]], ps[s]);
                    if (ns[s] != 0.f) atomicAdd(&g_n[rowG[s]], ns[s]);
                }
            }
        }

        // ---- col-side epilogue (off-diagonal jobs only) ----
        if (ti != tj) {
            float tmax = fmaxf(fmaxf(smaxf[0], smaxf[1]), fmaxf(smaxf[2], smaxf[3]));
            if (tmax > minM - 87.f) {                    // essentially never
                #pragma unroll
                for (int s = 0; s < 4; ++s) {
                    const int mt = s >> 1, rh = s & 1;
                    const int li = myLab[s];
                    #pragma unroll
                    for (int nt = 0; nt < 8; ++nt) {
                        float2 f2 = __half22float2(*(const __half2*)&acc[mt][nt][rh]);
                        #pragma unroll
                        for (int c = 0; c < 2; ++c) {
                            int ci = warp_n * 64 + nt * 8 + (lane & 3) * 2 + c;
                            float x = (c ? f2.y : f2.x) - g_M[colBase + ci];
                            if (x > -87.f) {
                                float e = __expf(x);
                                int lj = labels[colBase + ci];
                                bool pos = (li == 0) | (lj == li) | (lj == 0);
                                if (pos) atomicAdd(&g_p[colBase + ci], e);
                                else     atomicAdd(&g_n[colBase + ci], e);
                            }
                        }
                    }
                }
            }
        }

        ti = ni; tj = nj;
    }

    // -------- phase 2: last CTA to finish does the finalize --------
    __syncthreads();
    __shared__ int ticket_s;
    if (tid == 0) {
        __threadfence();
        ticket_s = atomicAdd(&g_done, 1);
    }
    __syncthreads();
    if (ticket_s == NCTA - 1) {
        __threadfence();
        float s0 = 0.f, s1 = 0.f, s2 = 0.f;
        int c0 = 0, c1 = 0, c2 = 0;
        for (int r = tid; r < NROWS; r += 256) {
            const int li = labels[r];
            const float P = g_p[r], Ng = g_n[r];
            const float loss = -logf((P + EPSL) / (P + Ng + EPSL));
            if (li == -1)     { s0 += loss; ++c0; }
            else if (li == 0) { s1 += loss; ++c1; }
            else              { s2 += loss; ++c2; }
        }
        __shared__ float sl[3];
        __shared__ int sc[3];
        if (tid < 3) { sl[tid] = 0.f; sc[tid] = 0; }
        __syncthreads();
        atomicAdd(&sl[0], s0); atomicAdd(&sl[1], s1); atomicAdd(&sl[2], s2);
        atomicAdd(&sc[0], c0); atomicAdd(&sc[1], c1); atomicAdd(&sc[2], c2);
        __syncthreads();
        if (tid == 0) {
            const int cm = sc[0], cz = sc[1], cp = sc[2];
            float total = 0.f, count = 0.f;
            if (cm - 1 + cz > 0) { total += sl[0]; count += (float)cm; }
            /* label 0 rows: pos count = NROWS-1 > 0 always */
            { total += sl[1]; count += (float)cz; }
            if (cp - 1 + cz > 0) { total += sl[2]; count += (float)cp; }
            out[0] = (count > 0.f) ? (total / fmaxf(count, 1.f)) : 0.f;
            g_done = 0;                                  // reset for next replay
            g_sync = 0;
            __threadfence();
        }
    }
}

extern "C" void kernel_launch(void* const* d_in, const int* in_sizes, int n_in,
                              void* d_out, int out_size) {
    const int*   labels = (const int*)d_in[0];
    const float* emb    = (const float*)d_in[1];
    float*       out    = (float*)d_out;

    cudaFuncSetAttribute(fused_kernel,
                         cudaFuncAttributeMaxDynamicSharedMemorySize, SMEM_BYTES);
    fused_kernel<<<NCTA, 256, SMEM_BYTES>>>(labels, emb, out);
}

// round 14
// speedup vs baseline: 1.0183x; 1.0183x over previous
#include <cuda_runtime.h>
#include <cuda_bf16.h>
#include <cuda_fp8.h>
#include <cuda_fp16.h>
#include <math.h>
#include <float.h>
#include <stdint.h>

#define NROWS 8192
#define DIM 128
#define N_TILES 64
#define NCTA 296                    // 2 CTAs/SM, one wave
#define EPSL 1e-8f

// fp8 tile: 128 rows x 128 bytes, padded to 144B rows (conflict-free ldmatrix)
#define AS 144
#define TILE_SM (128 * AS)          // 18432
#define OFF_A0 0
#define OFF_A1 TILE_SM
#define OFF_B0 (2 * TILE_SM)
#define OFF_B1 (3 * TILE_SM)
#define OFF_CLAB (4 * TILE_SM)      // 2 x 128 ints  (col labels per buffer)
#define OFF_CM   (OFF_CLAB + 1024)  // 2 x 128 floats (col Mref per buffer)
#define SMEM_BYTES (OFF_CM + 1024)  // 75776 -> 2 CTAs/SM fits 227KB

__device__ __align__(16) uint32_t g_f8[NROWS * DIM / 4];  // e4m3(e*sqrt2)
__device__ __align__(16) float g_M[NROWS];  // row softmax reference 2*|e_i|^2
__device__ float g_p[NROWS];
__device__ float g_n[NROWS];
__device__ int   g_done;

// ---------------- helpers (baseline PTX, valid on sm_103 target) ----------------
__device__ __forceinline__ uint32_t smem_u32(const void* p) {
    uint32_t a;
    asm("{ .reg .u64 t; cvta.to.shared.u64 t, %1; cvt.u32.u64 %0, t; }" : "=r"(a) : "l"(p));
    return a;
}
__device__ __forceinline__ void cpa16(uint32_t dst, const void* src) {
    asm volatile("cp.async.cg.shared.global [%0], [%1], 16;" :: "r"(dst), "l"(src));
}
__device__ __forceinline__ void ldsm4(uint32_t* r, uint32_t a) {
    asm volatile("ldmatrix.sync.aligned.m8n8.x4.shared.b16 {%0,%1,%2,%3}, [%4];"
                 : "=r"(r[0]), "=r"(r[1]), "=r"(r[2]), "=r"(r[3]) : "r"(a));
}
__device__ __forceinline__ void mma16832h(uint32_t* c, const uint32_t* a, const uint32_t* b) {
    asm volatile("mma.sync.aligned.m16n8k32.row.col.f16.e4m3.e4m3.f16 "
                 "{%0,%1}, {%2,%3,%4,%5}, {%6,%7}, {%0,%1};"
                 : "+r"(c[0]), "+r"(c[1])
                 : "r"(a[0]), "r"(a[1]), "r"(a[2]), "r"(a[3]), "r"(b[0]), "r"(b[1]));
}
__device__ __forceinline__ void mma16832h_z(uint32_t* c, const uint32_t* a, const uint32_t* b) {
    asm volatile("mma.sync.aligned.m16n8k32.row.col.f16.e4m3.e4m3.f16 "
                 "{%0,%1}, {%2,%3,%4,%5}, {%6,%7}, {%8,%8};"
                 : "=r"(c[0]), "=r"(c[1])
                 : "r"(a[0]), "r"(a[1]), "r"(a[2]), "r"(a[3]), "r"(b[0]), "r"(b[1]), "r"(0u));
}
__device__ __forceinline__ void copy_tile(uint32_t dstBase, const void* src, int tid) {
    #pragma unroll
    for (int jj = 0; jj < 4; ++jj) {
        int c = jj * 256 + tid;
        int row = c >> 3, col = c & 7;
        cpa16(dstBase + row * AS + col * 16, (const char*)src + row * 128 + col * 16);
    }
}
// B tile + its labels/M into buffer slot
__device__ __forceinline__ void load_B(uint32_t sb, int buf, int tj,
                                       const int* labels, int tid) {
    copy_tile(sb + (buf ? OFF_B1 : OFF_B0), (const char*)g_f8 + tj * 128 * DIM, tid);
    if (tid < 32)       cpa16(sb + OFF_CLAB + buf * 512 + tid * 16, labels + tj * 128 + tid * 4);
    else if (tid < 64)  cpa16(sb + OFF_CM + buf * 512 + (tid - 32) * 16, g_M + tj * 128 + (tid - 32) * 4);
}

// ---------------- kernel 1: fp32 -> e4m3*sqrt2, row norms, zero accumulators ----------------
__global__ void convert_kernel(const float* __restrict__ emb) {
    int idx = blockIdx.x * blockDim.x + threadIdx.x;     // warp <-> one row
    int row = idx >> 5;
    if (idx == 0) g_done = 0;
    float4 v = *(const float4*)&emb[idx * 4];
    const float s = 1.41421356237f;                      // folds 1/TEMPERATURE
    unsigned b0 = __nv_cvt_float_to_fp8(v.x * s, __NV_SATFINITE, __NV_E4M3);
    unsigned b1 = __nv_cvt_float_to_fp8(v.y * s, __NV_SATFINITE, __NV_E4M3);
    unsigned b2 = __nv_cvt_float_to_fp8(v.z * s, __NV_SATFINITE, __NV_E4M3);
    unsigned b3 = __nv_cvt_float_to_fp8(v.w * s, __NV_SATFINITE, __NV_E4M3);
    g_f8[idx] = b0 | (b1 << 8) | (b2 << 16) | (b3 << 24);

    float nr = v.x * v.x + v.y * v.y + v.z * v.z + v.w * v.w;
    #pragma unroll
    for (int o = 16; o; o >>= 1) nr += __shfl_xor_sync(0xffffffffu, nr, o);
    if ((idx & 31) == 0) {
        g_M[row] = 2.f * nr;      // row softmax reference (margin >= ~50)
        g_p[row] = 0.f;
        g_n[row] = 0.f;
    }
}

// ---------------- kernel 2: symmetric FP8 GEMM + guarded sums + inline finalize ----------------
__global__ __launch_bounds__(256, 2)
void sim_mma_kernel(const int* __restrict__ labels, float* __restrict__ out) {
    extern __shared__ unsigned char smem[];
    const uint32_t sb = smem_u32(smem);
    const int tid = threadIdx.x, lane = tid & 31, wid = tid >> 5;
    const int warp_m = wid & 3, warp_n = wid >> 2;       // 4 x 2 warp grid

    // job range: 2080 = 296*7 + 8 -> first 8 CTAs take 8 jobs
    const int b = blockIdx.x;
    const int g0 = b * 7 + (b < 8 ? b : 8);
    const int njobs = 7 + (b < 8 ? 1 : 0);

    int ti = 0, rem = g0;
    while (rem >= N_TILES - ti) { rem -= N_TILES - ti; ++ti; }
    int tj = ti + rem;

    int aCur = 0;                                        // A slot for current job
    copy_tile(sb + OFF_A0, (const char*)g_f8 + ti * 128 * DIM, tid);
    load_B(sb, 0, tj, labels, tid);
    asm volatile("cp.async.commit_group;");

    for (int k = 0; k < njobs; ++k) {
        const int buf = k & 1, nbuf = buf ^ 1;

        __syncthreads();                                 // nbuf consumers (job k-1) done

        // prefetch job k+1: B always; A only when row tile changes (other slot)
        int ni = ti, nj = tj + 1;
        if (nj == N_TILES) { ni = ti + 1; nj = ni; }
        int aNext = aCur;
        if (k + 1 < njobs) {
            load_B(sb, nbuf, nj, labels, tid);
            if (ni != ti) {
                aNext = aCur ^ 1;
                copy_tile(sb + (aNext ? OFF_A1 : OFF_A0),
                          (const char*)g_f8 + ni * 128 * DIM, tid);
            }
        }
        asm volatile("cp.async.commit_group;");
        asm volatile("cp.async.wait_group 1;");          // job k resident
        __syncthreads();

        // per-thread row info (L2-hot LDG)
        int rowG[4], myLab[4];
        float Mref[4];
        #pragma unroll
        for (int s = 0; s < 4; ++s) {
            rowG[s]  = ti * 128 + warp_m * 32 + (s >> 1) * 16 + (s & 1) * 8 + (lane >> 2);
            myLab[s] = labels[rowG[s]];
            Mref[s]  = g_M[rowG[s]];
        }

        // A fragments (reloaded per job -> no cross-job register residency)
        uint32_t af[2][4][4];
        {
            const uint32_t abase = sb + (aCur ? OFF_A1 : OFF_A0);
            const int arow = warp_m * 32 + (lane & 15);
            #pragma unroll
            for (int mt = 0; mt < 2; ++mt)
                #pragma unroll
                for (int ks = 0; ks < 4; ++ks)
                    ldsm4(af[mt][ks], abase + (arow + mt * 16) * AS + ks * 32 + (lane >> 4) * 16);
        }

        // ---- GEMM: 32x64 per warp, f16 accumulators ----
        uint32_t acc[2][8][2];
        const uint32_t bbase = sb + (buf ? OFF_B1 : OFF_B0);
        #pragma unroll
        for (int ks = 0; ks < 4; ++ks) {
            uint32_t bfr[8][2];
            #pragma unroll
            for (int np = 0; np < 4; ++np) {
                uint32_t r[4];
                uint32_t addr = bbase
                    + (warp_n * 64 + np * 16 + ((lane >> 4) & 1) * 8 + (lane & 7)) * AS
                    + ks * 32 + ((lane >> 3) & 1) * 16;
                ldsm4(r, addr);
                bfr[np * 2][0] = r[0]; bfr[np * 2][1] = r[1];
                bfr[np * 2 + 1][0] = r[2]; bfr[np * 2 + 1][1] = r[3];
            }
            #pragma unroll
            for (int mt = 0; mt < 2; ++mt)
                #pragma unroll
                for (int nt = 0; nt < 8; ++nt) {
                    if (ks == 0) mma16832h_z(acc[mt][nt], af[mt][0], bfr[nt]);
                    else         mma16832h(acc[mt][nt], af[mt][ks], bfr[nt]);
                }
        }

        const int* clab = (const int*)(smem + OFF_CLAB) + buf * 128;
        const float* cm = (const float*)(smem + OFF_CM) + buf * 128;
        const int colBase = tj * 128;

        // per-thread column guard threshold
        float minM = FLT_MAX;
        #pragma unroll
        for (int nt = 0; nt < 8; ++nt) {
            minM = fminf(minM, cm[warp_n * 64 + nt * 8 + (lane & 3) * 2]);
            minM = fminf(minM, cm[warp_n * 64 + nt * 8 + (lane & 3) * 2 + 1]);
        }

        // ---- row-side epilogue: packed-half max scan + rare slow path ----
        float smaxf[4];
        float ps[4] = {0.f,0.f,0.f,0.f}, ns[4] = {0.f,0.f,0.f,0.f};
        #pragma unroll
        for (int s = 0; s < 4; ++s) {
            const int mt = s >> 1, rh = s & 1;
            __half2 m2 = *(const __half2*)&acc[mt][0][rh];
            #pragma unroll
            for (int nt = 1; nt < 8; ++nt)
                m2 = __hmax2(m2, *(const __half2*)&acc[mt][nt][rh]);
            smaxf[s] = __half2float(__hmax(__low2half(m2), __high2half(m2)));
            if (smaxf[s] > Mref[s] - 87.f) {             // rare (diagonal tiles)
                const int rg = rowG[s], li = myLab[s];
                #pragma unroll
                for (int nt = 0; nt < 8; ++nt) {
                    float2 f2 = __half22float2(*(const __half2*)&acc[mt][nt][rh]);
                    #pragma unroll
                    for (int c = 0; c < 2; ++c) {
                        float x = (c ? f2.y : f2.x) - Mref[s];
                        if (x > -87.f) {
                            int ci = warp_n * 64 + nt * 8 + (lane & 3) * 2 + c;
                            if (colBase + ci != rg) {
                                float e = __expf(x);
                                int lj = clab[ci];
                                bool pos = (li == 0) | (lj == li) | (lj == 0);
                                if (pos) ps[s] += e; else ns[s] += e;
                            }
                        }
                    }
                }
            }
        }
        float any = ps[0]+ps[1]+ps[2]+ps[3]+ns[0]+ns[1]+ns[2]+ns[3];
        if (__any_sync(0xffffffffu, any != 0.f)) {
            #pragma unroll
            for (int s = 0; s < 4; ++s) {
                ps[s] += __shfl_xor_sync(0xffffffffu, ps[s], 1);
                ps[s] += __shfl_xor_sync(0xffffffffu, ps[s], 2);
                ns[s] += __shfl_xor_sync(0xffffffffu, ns[s], 1);
                ns[s] += __shfl_xor_sync(0xffffffffu, ns[s], 2);
                if ((lane & 3) == 0) {
                    if (ps[s] != 0.f) atomicAdd(&g_p[rowG[s]], ps[s]);
                    if (ns[s] != 0.f) atomicAdd(&g_n[rowG[s]], ns[s]);
                }
            }
        }

        // ---- col-side epilogue (off-diagonal jobs only) ----
        if (ti != tj) {
            float tmax = fmaxf(fmaxf(smaxf[0], smaxf[1]), fmaxf(smaxf[2], smaxf[3]));
            if (tmax > minM - 87.f) {                    // essentially never
                #pragma unroll
                for (int s = 0; s < 4; ++s) {
                    const int mt = s >> 1, rh = s & 1;
                    const int li = myLab[s];
                    #pragma unroll
                    for (int nt = 0; nt < 8; ++nt) {
                        float2 f2 = __half22float2(*(const __half2*)&acc[mt][nt][rh]);
                        #pragma unroll
                        for (int c = 0; c < 2; ++c) {
                            int ci = warp_n * 64 + nt * 8 + (lane & 3) * 2 + c;
                            float x = (c ? f2.y : f2.x) - cm[ci];
                            if (x > -87.f) {
                                float e = __expf(x);
                                int lj = clab[ci];
                                bool pos = (li == 0) | (lj == li) | (lj == 0);
                                if (pos) atomicAdd(&g_p[colBase + ci], e);
                                else     atomicAdd(&g_n[colBase + ci], e);
                            }
                        }
                    }
                }
            }
        }

        ti = ni; tj = nj; aCur = aNext;
    }

    // -------- inline finalize: last CTA to finish computes the scalar --------
    __syncthreads();
    __shared__ int ticket_s;
    if (tid == 0) {
        __threadfence();
        ticket_s = atomicAdd(&g_done, 1);
    }
    __syncthreads();
    if (ticket_s == NCTA - 1) {
        __threadfence();
        float s0 = 0.f, s1 = 0.f, s2 = 0.f;
        int c0 = 0, c1 = 0, c2 = 0;
        for (int r = tid; r < NROWS; r += 256) {
            const int li = labels[r];
            const float P = g_p[r], Ng = g_n[r];
            const float loss = -logf((P + EPSL) / (P + Ng + EPSL));
            if (li == -1)     { s0 += loss; ++c0; }
            else if (li == 0) { s1 += loss; ++c1; }
            else              { s2 += loss; ++c2; }
        }
        __shared__ float sl[3];
        __shared__ int sc[3];
        if (tid < 3) { sl[tid] = 0.f; sc[tid] = 0; }
        __syncthreads();
        atomicAdd(&sl[0], s0); atomicAdd(&sl[1], s1); atomicAdd(&sl[2], s2);
        atomicAdd(&sc[0], c0); atomicAdd(&sc[1], c1); atomicAdd(&sc[2], c2);
        __syncthreads();
        if (tid == 0) {
            const int cm_ = sc[0], cz = sc[1], cp = sc[2];
            float total = 0.f, count = 0.f;
            if (cm_ - 1 + cz > 0) { total += sl[0]; count += (float)cm_; }
            { total += sl[1]; count += (float)cz; }     // label 0: NROWS-1 > 0 always
            if (cp - 1 + cz > 0) { total += sl[2]; count += (float)cp; }
            out[0] = (count > 0.f) ? (total / fmaxf(count, 1.f)) : 0.f;
            g_done = 0;                                  // reset for graph replay
            __threadfence();
        }
    }
}

extern "C" void kernel_launch(void* const* d_in, const int* in_sizes, int n_in,
                              void* d_out, int out_size) {
    const int*   labels = (const int*)d_in[0];
    const float* emb    = (const float*)d_in[1];
    float*       out    = (float*)d_out;

    cudaFuncSetAttribute(sim_mma_kernel,
                         cudaFuncAttributeMaxDynamicSharedMemorySize, SMEM_BYTES);

    convert_kernel<<<NROWS * DIM / 1024, 256>>>(emb);
    sim_mma_kernel<<<NCTA, 256, SMEM_BYTES>>>(labels, out);
}

// round 15
// speedup vs baseline: 1.3431x; 1.3191x over previous
#include <cuda_runtime.h>
#include <cuda_bf16.h>
#include <cuda_fp8.h>
#include <cuda_fp16.h>
#include <math.h>
#include <float.h>
#include <stdint.h>

#define NROWS 8192
#define DIM 128
#define N_TILES 64
#define NCTA 296                    // 2 CTAs/SM, one wave
#define EPSL 1e-8f

// fp8 tile: 128 rows x 128 bytes, padded to 144B rows (conflict-free ldmatrix)
#define AS 144
#define TILE_SM (128 * AS)          // 18432
#define OFF_A0 0
#define OFF_A1 TILE_SM
#define OFF_B0 (2 * TILE_SM)
#define OFF_B1 (3 * TILE_SM)
#define SMEM_BYTES (4 * TILE_SM)    // 73728 -> 2 CTAs/SM fits

__device__ __align__(16) uint32_t g_f8[NROWS * DIM / 4];  // e4m3(e*sqrt2)
__device__ __align__(16) float g_M[NROWS];            // row softmax ref 2*|e_i|^2
__device__ __align__(16) float g_Mpmin[N_TILES * 8];  // per-tile per-pattern min M
__device__ float g_p[NROWS];
__device__ float g_n[NROWS];
__device__ int   g_cnt[3];
__device__ float g_lsum[3];
__device__ int   g_done;

// ---------------- helpers (baseline PTX, valid on sm_103 target) ----------------
__device__ __forceinline__ uint32_t smem_u32(const void* p) {
    uint32_t a;
    asm("{ .reg .u64 t; cvta.to.shared.u64 t, %1; cvt.u32.u64 %0, t; }" : "=r"(a) : "l"(p));
    return a;
}
__device__ __forceinline__ void cpa16(uint32_t dst, const void* src) {
    asm volatile("cp.async.cg.shared.global [%0], [%1], 16;" :: "r"(dst), "l"(src));
}
__device__ __forceinline__ void ldsm4(uint32_t* r, uint32_t a) {
    asm volatile("ldmatrix.sync.aligned.m8n8.x4.shared.b16 {%0,%1,%2,%3}, [%4];"
                 : "=r"(r[0]), "=r"(r[1]), "=r"(r[2]), "=r"(r[3]) : "r"(a));
}
__device__ __forceinline__ void mma16832h(uint32_t* c, const uint32_t* a, const uint32_t* b) {
    asm volatile("mma.sync.aligned.m16n8k32.row.col.f16.e4m3.e4m3.f16 "
                 "{%0,%1}, {%2,%3,%4,%5}, {%6,%7}, {%0,%1};"
                 : "+r"(c[0]), "+r"(c[1])
                 : "r"(a[0]), "r"(a[1]), "r"(a[2]), "r"(a[3]), "r"(b[0]), "r"(b[1]));
}
__device__ __forceinline__ void mma16832h_z(uint32_t* c, const uint32_t* a, const uint32_t* b) {
    asm volatile("mma.sync.aligned.m16n8k32.row.col.f16.e4m3.e4m3.f16 "
                 "{%0,%1}, {%2,%3,%4,%5}, {%6,%7}, {%8,%8};"
                 : "=r"(c[0]), "=r"(c[1])
                 : "r"(a[0]), "r"(a[1]), "r"(a[2]), "r"(a[3]), "r"(b[0]), "r"(b[1]), "r"(0u));
}
__device__ __forceinline__ void copy_tile(uint32_t dstBase, const void* src, int tid) {
    #pragma unroll
    for (int jj = 0; jj < 4; ++jj) {
        int c = jj * 256 + tid;
        int row = c >> 3, col = c & 7;
        cpa16(dstBase + row * AS + col * 16, (const char*)src + row * 128 + col * 16);
    }
}

// ---------------- kernel 1: tile-wise fp32 -> e4m3*sqrt2 + norms + pattern minima ----------------
__global__ __launch_bounds__(512)
void convert_kernel(const float* __restrict__ emb) {
    __shared__ float Msm[128];
    const int tid = threadIdx.x, lane = tid & 31, wid = tid >> 5;
    const int b = blockIdx.x;                   // one 128-row tile per block
    if (b == 0 && tid < 7) {                    // zero finalize state
        if (tid < 3)      g_cnt[tid] = 0;
        else if (tid < 6) g_lsum[tid - 3] = 0.f;
        else              g_done = 0;
    }
    const float4* e4 = (const float4*)emb;
    const float s = 1.41421356237f;             // folds 1/TEMPERATURE
    #pragma unroll
    for (int rr = 0; rr < 8; ++rr) {            // 16 warps x 8 rows
        const int rl = wid * 8 + rr;
        const int row = b * 128 + rl;
        float4 v = e4[row * 32 + lane];
        unsigned b0 = __nv_cvt_float_to_fp8(v.x * s, __NV_SATFINITE, __NV_E4M3);
        unsigned b1 = __nv_cvt_float_to_fp8(v.y * s, __NV_SATFINITE, __NV_E4M3);
        unsigned b2 = __nv_cvt_float_to_fp8(v.z * s, __NV_SATFINITE, __NV_E4M3);
        unsigned b3 = __nv_cvt_float_to_fp8(v.w * s, __NV_SATFINITE, __NV_E4M3);
        g_f8[row * 32 + lane] = b0 | (b1 << 8) | (b2 << 16) | (b3 << 24);
        float nr = v.x * v.x + v.y * v.y + v.z * v.z + v.w * v.w;
        #pragma unroll
        for (int o = 16; o; o >>= 1) nr += __shfl_xor_sync(0xffffffffu, nr, o);
        if (lane == 0) {
            float M = 2.f * nr;                 // true row max (margin >= ~50)
            Msm[rl] = M;
            g_M[row] = M;
            g_p[row] = 0.f;
            g_n[row] = 0.f;
        }
    }
    __syncthreads();
    if (tid < 8) {                              // pattern (wn, q) minima
        const int wn = tid >> 2, q = tid & 3;
        float m = FLT_MAX;
        #pragma unroll
        for (int nt = 0; nt < 8; ++nt) {
            m = fminf(m, Msm[wn * 64 + nt * 8 + q * 2]);
            m = fminf(m, Msm[wn * 64 + nt * 8 + q * 2 + 1]);
        }
        g_Mpmin[b * 8 + tid] = m;
    }
}

// ---------------- kernel 2: symmetric FP8 GEMM (f16 acc) + two-sided guarded sums ----------------
__global__ __launch_bounds__(256, 2)
void sim_mma_kernel(const int* __restrict__ labels) {
    extern __shared__ unsigned char smem[];
    const uint32_t sb = smem_u32(smem);
    const int tid = threadIdx.x, lane = tid & 31, wid = tid >> 5;
    const int warp_m = wid & 3, warp_n = wid >> 2;       // 4 x 2 warp grid

    // job range: 2080 = 296*7 + 8 -> first 8 CTAs take 8 jobs
    const int b = blockIdx.x;
    const int g0 = b * 7 + (b < 8 ? b : 8);
    const int njobs = 7 + (b < 8 ? 1 : 0);

    int ti = 0, rem = g0;
    while (rem >= N_TILES - ti) { rem -= N_TILES - ti; ++ti; }
    int tj = ti + rem;

    copy_tile(sb + OFF_A0, (const char*)g_f8 + ti * 128 * DIM, tid);
    copy_tile(sb + OFF_B0, (const char*)g_f8 + tj * 128 * DIM, tid);
    asm volatile("cp.async.commit_group;");

    for (int k = 0; k < njobs; ++k) {
        const int buf = k & 1, nbuf = buf ^ 1;

        __syncthreads();                                 // nbuf consumers (job k-1) done
        int ni = ti, nj = tj + 1;
        if (nj == N_TILES) { ni = ti + 1; nj = ni; }
        if (k + 1 < njobs) {
            copy_tile(sb + (nbuf ? OFF_A1 : OFF_A0), (const char*)g_f8 + ni * 128 * DIM, tid);
            copy_tile(sb + (nbuf ? OFF_B1 : OFF_B0), (const char*)g_f8 + nj * 128 * DIM, tid);
        }
        asm volatile("cp.async.commit_group;");
        asm volatile("cp.async.wait_group 1;");          // job k resident
        __syncthreads();

        // per-thread row info + column guard threshold (all L2-hot LDG)
        const float minM = g_Mpmin[tj * 8 + warp_n * 4 + (lane & 3)];
        int rowG[4], myLab[4];
        float Mref[4];
        #pragma unroll
        for (int s = 0; s < 4; ++s) {
            rowG[s]  = ti * 128 + warp_m * 32 + (s >> 1) * 16 + (s & 1) * 8 + (lane >> 2);
            myLab[s] = labels[rowG[s]];
            Mref[s]  = g_M[rowG[s]];
        }

        // A fragments (reloaded per job -> no cross-job register residency)
        uint32_t af[2][4][4];
        {
            const uint32_t abase = sb + (buf ? OFF_A1 : OFF_A0);
            const int arow = warp_m * 32 + (lane & 15);
            #pragma unroll
            for (int mt = 0; mt < 2; ++mt)
                #pragma unroll
                for (int ks = 0; ks < 4; ++ks)
                    ldsm4(af[mt][ks], abase + (arow + mt * 16) * AS + ks * 32 + (lane >> 4) * 16);
        }

        // ---- GEMM: 32x64 per warp, f16 accumulators ----
        uint32_t acc[2][8][2];
        const uint32_t bbase = sb + (buf ? OFF_B1 : OFF_B0);
        #pragma unroll
        for (int ks = 0; ks < 4; ++ks) {
            uint32_t bfr[8][2];
            #pragma unroll
            for (int np = 0; np < 4; ++np) {
                uint32_t r[4];
                uint32_t addr = bbase
                    + (warp_n * 64 + np * 16 + ((lane >> 4) & 1) * 8 + (lane & 7)) * AS
                    + ks * 32 + ((lane >> 3) & 1) * 16;
                ldsm4(r, addr);
                bfr[np * 2][0] = r[0]; bfr[np * 2][1] = r[1];
                bfr[np * 2 + 1][0] = r[2]; bfr[np * 2 + 1][1] = r[3];
            }
            #pragma unroll
            for (int mt = 0; mt < 2; ++mt)
                #pragma unroll
                for (int nt = 0; nt < 8; ++nt) {
                    if (ks == 0) mma16832h_z(acc[mt][nt], af[mt][0], bfr[nt]);
                    else         mma16832h(acc[mt][nt], af[mt][ks], bfr[nt]);
                }
        }

        const int colBase = tj * 128;

        // ---- row-side epilogue: packed-half max scan + rare slow path ----
        float smaxf[4];
        float ps[4] = {0.f,0.f,0.f,0.f}, ns[4] = {0.f,0.f,0.f,0.f};
        #pragma unroll
        for (int s = 0; s < 4; ++s) {
            const int mt = s >> 1, rh = s & 1;
            __half2 m2 = *(const __half2*)&acc[mt][0][rh];
            #pragma unroll
            for (int nt = 1; nt < 8; ++nt)
                m2 = __hmax2(m2, *(const __half2*)&acc[mt][nt][rh]);
            smaxf[s] = __half2float(__hmax(__low2half(m2), __high2half(m2)));
            if (smaxf[s] > Mref[s] - 87.f) {             // rare (diagonal tiles)
                const int rg = rowG[s], li = myLab[s];
                #pragma unroll
                for (int nt = 0; nt < 8; ++nt) {
                    float2 f2 = __half22float2(*(const __half2*)&acc[mt][nt][rh]);
                    #pragma unroll
                    for (int c = 0; c < 2; ++c) {
                        float x = (c ? f2.y : f2.x) - Mref[s];
                        if (x > -87.f) {
                            int ci = warp_n * 64 + nt * 8 + (lane & 3) * 2 + c;
                            if (colBase + ci != rg) {
                                float e = __expf(x);
                                int lj = labels[colBase + ci];   // L2-hot
                                bool pos = (li == 0) | (lj == li) | (lj == 0);
                                if (pos) ps[s] += e; else ns[s] += e;
                            }
                        }
                    }
                }
            }
        }
        float any = ps[0]+ps[1]+ps[2]+ps[3]+ns[0]+ns[1]+ns[2]+ns[3];
        if (__any_sync(0xffffffffu, any != 0.f)) {
            #pragma unroll
            for (int s = 0; s < 4; ++s) {
                ps[s] += __shfl_xor_sync(0xffffffffu, ps[s], 1);
                ps[s] += __shfl_xor_sync(0xffffffffu, ps[s], 2);
                ns[s] += __shfl_xor_sync(0xffffffffu, ns[s], 1);
                ns[s] += __shfl_xor_sync(0xffffffffu, ns[s], 2);
                if ((lane & 3) == 0) {
                    if (ps[s] != 0.f) atomicAdd(&g_p[rowG[s]], ps[s]);
                    if (ns[s] != 0.f) atomicAdd(&g_n[rowG[s]], ns[s]);
                }
            }
        }

        // ---- col-side epilogue (off-diagonal jobs only) ----
        if (ti != tj) {
            float tmax = fmaxf(fmaxf(smaxf[0], smaxf[1]), fmaxf(smaxf[2], smaxf[3]));
            if (tmax > minM - 87.f) {                    // essentially never
                #pragma unroll
                for (int s = 0; s < 4; ++s) {
                    const int mt = s >> 1, rh = s & 1;
                    const int li = myLab[s];
                    #pragma unroll
                    for (int nt = 0; nt < 8; ++nt) {
                        float2 f2 = __half22float2(*(const __half2*)&acc[mt][nt][rh]);
                        #pragma unroll
                        for (int c = 0; c < 2; ++c) {
                            int ci = warp_n * 64 + nt * 8 + (lane & 3) * 2 + c;
                            float x = (c ? f2.y : f2.x) - g_M[colBase + ci];
                            if (x > -87.f) {
                                float e = __expf(x);
                                int lj = labels[colBase + ci];
                                bool pos = (li == 0) | (lj == li) | (lj == 0);
                                if (pos) atomicAdd(&g_p[colBase + ci], e);
                                else     atomicAdd(&g_n[colBase + ci], e);
                            }
                        }
                    }
                }
            }
        }

        ti = ni; tj = nj;
    }
}

// ---------------- kernel 3: fused hist + per-label loss sums + output ----------------
__global__ void finalize_kernel(const int* __restrict__ labels, float* __restrict__ out) {
    __shared__ float sl[3];
    __shared__ int sc[3];
    const int tid = threadIdx.x;
    if (tid < 3) { sl[tid] = 0.f; sc[tid] = 0; }
    __syncthreads();

    const int r = blockIdx.x * 256 + tid;
    const int li = labels[r];
    const float P = g_p[r], Ng = g_n[r];
    const float loss = -logf((P + EPSL) / (P + Ng + EPSL));
    atomicAdd(&sl[li + 1], loss);
    atomicAdd(&sc[li + 1], 1);
    __syncthreads();

    if (tid < 3) {
        atomicAdd(&g_lsum[tid], sl[tid]);
        atomicAdd(&g_cnt[tid], sc[tid]);
    }
    __threadfence();
    __syncthreads();

    if (tid == 0) {
        int ticket = atomicAdd(&g_done, 1);
        if (ticket == gridDim.x - 1) {                   // last block finishing
            int cm = g_cnt[0], c0 = g_cnt[1], cp = g_cnt[2];
            float total = 0.f, count = 0.f;
            if (cm - 1 + c0 > 0) { total += g_lsum[0]; count += (float)cm; }
            { total += g_lsum[1]; count += (float)c0; } // label 0: NROWS-1 > 0 always
            if (cp - 1 + c0 > 0) { total += g_lsum[2]; count += (float)cp; }
            out[0] = (count > 0.f) ? (total / fmaxf(count, 1.f)) : 0.f;
        }
    }
}

extern "C" void kernel_launch(void* const* d_in, const int* in_sizes, int n_in,
                              void* d_out, int out_size) {
    const int*   labels = (const int*)d_in[0];
    const float* emb    = (const float*)d_in[1];
    float*       out    = (float*)d_out;

    cudaFuncSetAttribute(sim_mma_kernel,
                         cudaFuncAttributeMaxDynamicSharedMemorySize, SMEM_BYTES);

    convert_kernel<<<N_TILES, 512>>>(emb);
    sim_mma_kernel<<<NCTA, 256, SMEM_BYTES>>>(labels);
    finalize_kernel<<<NROWS / 256, 256>>>(labels, out);
}

// round 16
// speedup vs baseline: 1.5375x; 1.1447x over previous
#include <cuda_runtime.h>
#include <cuda_bf16.h>
#include <cuda_fp8.h>
#include <cuda_fp16.h>
#include <math.h>
#include <float.h>
#include <stdint.h>

#define NROWS 8192
#define DIM 128
#define N_TILES 64
#define NCTA 296                    // 2 CTAs/SM, one wave
#define EPSL 1e-8f

// fp8 tile: 128 rows x 128 bytes, padded to 144B rows (conflict-free ldmatrix)
#define AS 144
#define TILE_SM (128 * AS)          // 18432
#define OFF_A0 0
#define OFF_A1 TILE_SM
#define OFF_B0 (2 * TILE_SM)
#define OFF_B1 (3 * TILE_SM)
#define OFF_CLAB (4 * TILE_SM)      // 2 x 128 ints  (col labels per buffer)
#define OFF_CM   (OFF_CLAB + 1024)  // 2 x 128 floats (col Mref per buffer)
#define SMEM_BYTES (OFF_CM + 1024)  // 75776 -> 2 CTAs/SM fits 227KB

__device__ __align__(16) uint32_t g_f8[NROWS * DIM / 4];  // e4m3(e*sqrt2)
__device__ __align__(16) float g_M[NROWS];  // row softmax reference 2*|e_i|^2
__device__ float g_p[NROWS];
__device__ float g_n[NROWS];
__device__ int   g_cnt[3];
__device__ float g_lsum[3];
__device__ int   g_done;

// ---------------- helpers (baseline PTX, valid on sm_103 target) ----------------
__device__ __forceinline__ uint32_t smem_u32(const void* p) {
    uint32_t a;
    asm("{ .reg .u64 t; cvta.to.shared.u64 t, %1; cvt.u32.u64 %0, t; }" : "=r"(a) : "l"(p));
    return a;
}
__device__ __forceinline__ void cpa16(uint32_t dst, const void* src) {
    asm volatile("cp.async.cg.shared.global [%0], [%1], 16;" :: "r"(dst), "l"(src));
}
__device__ __forceinline__ void ldsm4(uint32_t* r, uint32_t a) {
    asm volatile("ldmatrix.sync.aligned.m8n8.x4.shared.b16 {%0,%1,%2,%3}, [%4];"
                 : "=r"(r[0]), "=r"(r[1]), "=r"(r[2]), "=r"(r[3]) : "r"(a));
}
__device__ __forceinline__ void mma16832h(uint32_t* c, const uint32_t* a, const uint32_t* b) {
    asm volatile("mma.sync.aligned.m16n8k32.row.col.f16.e4m3.e4m3.f16 "
                 "{%0,%1}, {%2,%3,%4,%5}, {%6,%7}, {%0,%1};"
                 : "+r"(c[0]), "+r"(c[1])
                 : "r"(a[0]), "r"(a[1]), "r"(a[2]), "r"(a[3]), "r"(b[0]), "r"(b[1]));
}
__device__ __forceinline__ void mma16832h_z(uint32_t* c, const uint32_t* a, const uint32_t* b) {
    asm volatile("mma.sync.aligned.m16n8k32.row.col.f16.e4m3.e4m3.f16 "
                 "{%0,%1}, {%2,%3,%4,%5}, {%6,%7}, {%8,%8};"
                 : "=r"(c[0]), "=r"(c[1])
                 : "r"(a[0]), "r"(a[1]), "r"(a[2]), "r"(a[3]), "r"(b[0]), "r"(b[1]), "r"(0u));
}
__device__ __forceinline__ void copy_tile(uint32_t dstBase, const void* src, int tid) {
    #pragma unroll
    for (int jj = 0; jj < 4; ++jj) {
        int c = jj * 256 + tid;
        int row = c >> 3, col = c & 7;
        cpa16(dstBase + row * AS + col * 16, (const char*)src + row * 128 + col * 16);
    }
}
__device__ __forceinline__ void load_job(uint32_t sb, int buf, int ti, int tj,
                                         const int* labels, int tid) {
    copy_tile(sb + (buf ? OFF_A1 : OFF_A0), (const char*)g_f8 + ti * 128 * DIM, tid);
    copy_tile(sb + (buf ? OFF_B1 : OFF_B0), (const char*)g_f8 + tj * 128 * DIM, tid);
    if (tid < 32)       cpa16(sb + OFF_CLAB + buf * 512 + tid * 16, labels + tj * 128 + tid * 4);
    else if (tid < 64)  cpa16(sb + OFF_CM + buf * 512 + (tid - 32) * 16, g_M + tj * 128 + (tid - 32) * 4);
}

// ---------------- kernel 1: fp32 -> e4m3*sqrt2 (2-row ILP) + norms + zero accums ----------------
__global__ void convert_kernel(const float* __restrict__ emb) {
    const int idx = blockIdx.x * blockDim.x + threadIdx.x;   // 131072 threads
    const int lane = idx & 31;
    const int row0 = idx >> 5;                               // 0..4095
    const int row1 = row0 + (NROWS / 2);
    if (idx < 7) {                                           // zero finalize state
        if (idx < 3)      g_cnt[idx] = 0;
        else if (idx < 6) g_lsum[idx - 3] = 0.f;
        else              g_done = 0;
    }
    const float4* e4 = (const float4*)emb;
    const float s = 1.41421356237f;                          // folds 1/TEMPERATURE
    float4 v0 = e4[row0 * 32 + lane];                        // two independent chains
    float4 v1 = e4[row1 * 32 + lane];

    unsigned a0 = __nv_cvt_float_to_fp8(v0.x * s, __NV_SATFINITE, __NV_E4M3);
    unsigned a1 = __nv_cvt_float_to_fp8(v0.y * s, __NV_SATFINITE, __NV_E4M3);
    unsigned a2 = __nv_cvt_float_to_fp8(v0.z * s, __NV_SATFINITE, __NV_E4M3);
    unsigned a3 = __nv_cvt_float_to_fp8(v0.w * s, __NV_SATFINITE, __NV_E4M3);
    g_f8[row0 * 32 + lane] = a0 | (a1 << 8) | (a2 << 16) | (a3 << 24);
    unsigned b0 = __nv_cvt_float_to_fp8(v1.x * s, __NV_SATFINITE, __NV_E4M3);
    unsigned b1 = __nv_cvt_float_to_fp8(v1.y * s, __NV_SATFINITE, __NV_E4M3);
    unsigned b2 = __nv_cvt_float_to_fp8(v1.z * s, __NV_SATFINITE, __NV_E4M3);
    unsigned b3 = __nv_cvt_float_to_fp8(v1.w * s, __NV_SATFINITE, __NV_E4M3);
    g_f8[row1 * 32 + lane] = b0 | (b1 << 8) | (b2 << 16) | (b3 << 24);

    float n0 = v0.x * v0.x + v0.y * v0.y + v0.z * v0.z + v0.w * v0.w;
    float n1 = v1.x * v1.x + v1.y * v1.y + v1.z * v1.z + v1.w * v1.w;
    #pragma unroll
    for (int o = 16; o; o >>= 1) {                           // interleaved chains
        n0 += __shfl_xor_sync(0xffffffffu, n0, o);
        n1 += __shfl_xor_sync(0xffffffffu, n1, o);
    }
    if (lane == 0) {
        g_M[row0] = 2.f * n0;     // row softmax reference (margin >= ~50)
        g_p[row0] = 0.f;
        g_n[row0] = 0.f;
        g_M[row1] = 2.f * n1;
        g_p[row1] = 0.f;
        g_n[row1] = 0.f;
    }
}

// ---------------- kernel 2: symmetric FP8 GEMM (f16 acc) + two-sided guarded sums ----------------
// (byte-identical to the 41.7us Round-10 winner)
__global__ __launch_bounds__(256, 2)
void sim_mma_kernel(const int* __restrict__ labels) {
    extern __shared__ unsigned char smem[];
    const uint32_t sb = smem_u32(smem);
    const int tid = threadIdx.x, lane = tid & 31, wid = tid >> 5;
    const int warp_m = wid & 3, warp_n = wid >> 2;       // 4 x 2 warp grid

    // job range: 2080 = 296*7 + 8 -> first 8 CTAs take 8 jobs
    const int b = blockIdx.x;
    const int g0 = b * 7 + (b < 8 ? b : 8);
    const int njobs = 7 + (b < 8 ? 1 : 0);

    int ti = 0, rem = g0;
    while (rem >= N_TILES - ti) { rem -= N_TILES - ti; ++ti; }
    int tj = ti + rem;

    load_job(sb, 0, ti, tj, labels, tid);
    asm volatile("cp.async.commit_group;");

    for (int k = 0; k < njobs; ++k) {
        const int buf = k & 1, nbuf = buf ^ 1;

        __syncthreads();                                 // nbuf consumers (job k-1) done
        int ni = ti, nj = tj + 1;
        if (nj == N_TILES) { ni = ti + 1; nj = ni; }
        if (k + 1 < njobs) load_job(sb, nbuf, ni, nj, labels, tid);
        asm volatile("cp.async.commit_group;");
        asm volatile("cp.async.wait_group 1;");          // job k resident
        __syncthreads();

        // per-thread row info (L2-hot LDG)
        int rowG[4], myLab[4];
        float Mref[4];
        #pragma unroll
        for (int s = 0; s < 4; ++s) {
            rowG[s]  = ti * 128 + warp_m * 32 + (s >> 1) * 16 + (s & 1) * 8 + (lane >> 2);
            myLab[s] = labels[rowG[s]];
            Mref[s]  = g_M[rowG[s]];
        }

        // A fragments
        uint32_t af[2][4][4];
        {
            const uint32_t abase = sb + (buf ? OFF_A1 : OFF_A0);
            const int arow = warp_m * 32 + (lane & 15);
            #pragma unroll
            for (int mt = 0; mt < 2; ++mt)
                #pragma unroll
                for (int ks = 0; ks < 4; ++ks)
                    ldsm4(af[mt][ks], abase + (arow + mt * 16) * AS + ks * 32 + (lane >> 4) * 16);
        }

        // ---- GEMM: 32x64 per warp, f16 accumulators ----
        uint32_t acc[2][8][2];
        const uint32_t bbase = sb + (buf ? OFF_B1 : OFF_B0);
        #pragma unroll
        for (int ks = 0; ks < 4; ++ks) {
            uint32_t bfr[8][2];
            #pragma unroll
            for (int np = 0; np < 4; ++np) {
                uint32_t r[4];
                uint32_t addr = bbase
                    + (warp_n * 64 + np * 16 + ((lane >> 4) & 1) * 8 + (lane & 7)) * AS
                    + ks * 32 + ((lane >> 3) & 1) * 16;
                ldsm4(r, addr);
                bfr[np * 2][0] = r[0]; bfr[np * 2][1] = r[1];
                bfr[np * 2 + 1][0] = r[2]; bfr[np * 2 + 1][1] = r[3];
            }
            #pragma unroll
            for (int mt = 0; mt < 2; ++mt)
                #pragma unroll
                for (int nt = 0; nt < 8; ++nt) {
                    if (ks == 0) mma16832h_z(acc[mt][nt], af[mt][0], bfr[nt]);
                    else         mma16832h(acc[mt][nt], af[mt][ks], bfr[nt]);
                }
        }

        const int* clab = (const int*)(smem + OFF_CLAB) + buf * 128;
        const float* cm = (const float*)(smem + OFF_CM) + buf * 128;
        const int colBase = tj * 128;

        // per-thread column guard threshold
        float minM = FLT_MAX;
        #pragma unroll
        for (int nt = 0; nt < 8; ++nt) {
            minM = fminf(minM, cm[warp_n * 64 + nt * 8 + (lane & 3) * 2]);
            minM = fminf(minM, cm[warp_n * 64 + nt * 8 + (lane & 3) * 2 + 1]);
        }

        // ---- row-side epilogue: packed-half max scan + rare slow path ----
        float smaxf[4];
        float ps[4] = {0.f,0.f,0.f,0.f}, ns[4] = {0.f,0.f,0.f,0.f};
        #pragma unroll
        for (int s = 0; s < 4; ++s) {
            const int mt = s >> 1, rh = s & 1;
            __half2 m2 = *(const __half2*)&acc[mt][0][rh];
            #pragma unroll
            for (int nt = 1; nt < 8; ++nt)
                m2 = __hmax2(m2, *(const __half2*)&acc[mt][nt][rh]);
            smaxf[s] = __half2float(__hmax(__low2half(m2), __high2half(m2)));
            if (smaxf[s] > Mref[s] - 87.f) {             // rare (diagonal tiles)
                const int rg = rowG[s], li = myLab[s];
                #pragma unroll
                for (int nt = 0; nt < 8; ++nt) {
                    float2 f2 = __half22float2(*(const __half2*)&acc[mt][nt][rh]);
                    #pragma unroll
                    for (int c = 0; c < 2; ++c) {
                        float x = (c ? f2.y : f2.x) - Mref[s];
                        if (x > -87.f) {
                            int ci = warp_n * 64 + nt * 8 + (lane & 3) * 2 + c;
                            if (colBase + ci != rg) {
                                float e = __expf(x);
                                int lj = clab[ci];
                                bool pos = (li == 0) | (lj == li) | (lj == 0);
                                if (pos) ps[s] += e; else ns[s] += e;
                            }
                        }
                    }
                }
            }
        }
        float any = ps[0]+ps[1]+ps[2]+ps[3]+ns[0]+ns[1]+ns[2]+ns[3];
        if (__any_sync(0xffffffffu, any != 0.f)) {
            #pragma unroll
            for (int s = 0; s < 4; ++s) {
                ps[s] += __shfl_xor_sync(0xffffffffu, ps[s], 1);
                ps[s] += __shfl_xor_sync(0xffffffffu, ps[s], 2);
                ns[s] += __shfl_xor_sync(0xffffffffu, ns[s], 1);
                ns[s] += __shfl_xor_sync(0xffffffffu, ns[s], 2);
                if ((lane & 3) == 0) {
                    if (ps[s] != 0.f) atomicAdd(&g_p[rowG[s]], ps[s]);
                    if (ns[s] != 0.f) atomicAdd(&g_n[rowG[s]], ns[s]);
                }
            }
        }

        // ---- col-side epilogue (off-diagonal jobs only) ----
        if (ti != tj) {
            float tmax = fmaxf(fmaxf(smaxf[0], smaxf[1]), fmaxf(smaxf[2], smaxf[3]));
            if (tmax > minM - 87.f) {                    // essentially never
                #pragma unroll
                for (int s = 0; s < 4; ++s) {
                    const int mt = s >> 1, rh = s & 1;
                    const int li = myLab[s];
                    #pragma unroll
                    for (int nt = 0; nt < 8; ++nt) {
                        float2 f2 = __half22float2(*(const __half2*)&acc[mt][nt][rh]);
                        #pragma unroll
                        for (int c = 0; c < 2; ++c) {
                            int ci = warp_n * 64 + nt * 8 + (lane & 3) * 2 + c;
                            float x = (c ? f2.y : f2.x) - cm[ci];
                            if (x > -87.f) {
                                float e = __expf(x);
                                int lj = clab[ci];
                                bool pos = (li == 0) | (lj == li) | (lj == 0);
                                if (pos) atomicAdd(&g_p[colBase + ci], e);
                                else     atomicAdd(&g_n[colBase + ci], e);
                            }
                        }
                    }
                }
            }
        }

        ti = ni; tj = nj;
    }
}

// ---------------- kernel 3: finalize via warp shfl reductions (no smem-atomic hotspot) ----------------
__global__ void finalize_kernel(const int* __restrict__ labels, float* __restrict__ out) {
    const int tid = threadIdx.x, lane = tid & 31;
    const int r = blockIdx.x * 256 + tid;
    const int li = labels[r];
    const float P = g_p[r], Ng = g_n[r];
    const float loss = -logf((P + EPSL) / (P + Ng + EPSL));

    float s0 = (li == -1) ? loss : 0.f;
    float s1 = (li ==  0) ? loss : 0.f;
    float s2 = (li ==  1) ? loss : 0.f;
    unsigned bm = __ballot_sync(0xffffffffu, li == -1);
    unsigned bz = __ballot_sync(0xffffffffu, li ==  0);
    unsigned bp = __ballot_sync(0xffffffffu, li ==  1);
    #pragma unroll
    for (int o = 16; o; o >>= 1) {
        s0 += __shfl_xor_sync(0xffffffffu, s0, o);
        s1 += __shfl_xor_sync(0xffffffffu, s1, o);
        s2 += __shfl_xor_sync(0xffffffffu, s2, o);
    }
    if (lane == 0) {
        atomicAdd(&g_lsum[0], s0);
        atomicAdd(&g_lsum[1], s1);
        atomicAdd(&g_lsum[2], s2);
        atomicAdd(&g_cnt[0], (int)__popc(bm));
        atomicAdd(&g_cnt[1], (int)__popc(bz));
        atomicAdd(&g_cnt[2], (int)__popc(bp));
    }
    __threadfence();
    __syncthreads();

    if (tid == 0) {
        int ticket = atomicAdd(&g_done, 1);
        if (ticket == gridDim.x - 1) {                   // last block finishing
            int cm = g_cnt[0], c0 = g_cnt[1], cp = g_cnt[2];
            float total = 0.f, count = 0.f;
            if (cm - 1 + c0 > 0) { total += g_lsum[0]; count += (float)cm; }
            { total += g_lsum[1]; count += (float)c0; } // label 0: NROWS-1 > 0 always
            if (cp - 1 + c0 > 0) { total += g_lsum[2]; count += (float)cp; }
            out[0] = (count > 0.f) ? (total / fmaxf(count, 1.f)) : 0.f;
        }
    }
}

extern "C" void kernel_launch(void* const* d_in, const int* in_sizes, int n_in,
                              void* d_out, int out_size) {
    const int*   labels = (const int*)d_in[0];
    const float* emb    = (const float*)d_in[1];
    float*       out    = (float*)d_out;

    cudaFuncSetAttribute(sim_mma_kernel,
                         cudaFuncAttributeMaxDynamicSharedMemorySize, SMEM_BYTES);

    convert_kernel<<<NROWS * 32 / 2 / 256, 256>>>(emb);
    sim_mma_kernel<<<NCTA, 256, SMEM_BYTES>>>(labels);
    finalize_kernel<<<NROWS / 256, 256>>>(labels, out);
}

// round 17
// speedup vs baseline: 1.6299x; 1.0601x over previous
#include <cuda_runtime.h>
#include <cuda_bf16.h>
#include <cuda_fp8.h>
#include <cuda_fp16.h>
#include <math.h>
#include <float.h>
#include <stdint.h>

#define NROWS 8192
#define DIM 128
#define N_TILES 64
#define NCTA 296                    // 2 CTAs/SM, one wave
#define EPSL 1e-8f

// fp8 tile: 128 rows x 128 bytes, padded to 144B rows (conflict-free ldmatrix)
#define AS 144
#define TILE_SM (128 * AS)          // 18432
#define OFF_A0 0                    // A: 2 parity slots
#define OFF_B  (2 * TILE_SM)        // B: 3 slots (triple buffer)
#define OFF_CLAB (5 * TILE_SM)      // 3 x 128 ints
#define OFF_CM   (OFF_CLAB + 1536)  // 3 x 128 floats
#define SMEM_BYTES (OFF_CM + 1536)  // 95232 -> 2 CTAs/SM = 190464 fits

__device__ __align__(16) uint32_t g_f8[NROWS * DIM / 4];  // e4m3(e*sqrt2)
__device__ __align__(16) float g_M[NROWS];  // row softmax reference 2*|e_i|^2
__device__ float g_p[NROWS];
__device__ float g_n[NROWS];
__device__ int   g_cnt[3];
__device__ float g_lsum[3];
__device__ int   g_done;

// ---------------- helpers (baseline PTX, valid on sm_103 target) ----------------
__device__ __forceinline__ uint32_t smem_u32(const void* p) {
    uint32_t a;
    asm("{ .reg .u64 t; cvta.to.shared.u64 t, %1; cvt.u32.u64 %0, t; }" : "=r"(a) : "l"(p));
    return a;
}
__device__ __forceinline__ void cpa16(uint32_t dst, const void* src) {
    asm volatile("cp.async.cg.shared.global [%0], [%1], 16;" :: "r"(dst), "l"(src));
}
__device__ __forceinline__ void ldsm4(uint32_t* r, uint32_t a) {
    asm volatile("ldmatrix.sync.aligned.m8n8.x4.shared.b16 {%0,%1,%2,%3}, [%4];"
                 : "=r"(r[0]), "=r"(r[1]), "=r"(r[2]), "=r"(r[3]) : "r"(a));
}
__device__ __forceinline__ void mma16832h(uint32_t* c, const uint32_t* a, const uint32_t* b) {
    asm volatile("mma.sync.aligned.m16n8k32.row.col.f16.e4m3.e4m3.f16 "
                 "{%0,%1}, {%2,%3,%4,%5}, {%6,%7}, {%0,%1};"
                 : "+r"(c[0]), "+r"(c[1])
                 : "r"(a[0]), "r"(a[1]), "r"(a[2]), "r"(a[3]), "r"(b[0]), "r"(b[1]));
}
__device__ __forceinline__ void mma16832h_z(uint32_t* c, const uint32_t* a, const uint32_t* b) {
    asm volatile("mma.sync.aligned.m16n8k32.row.col.f16.e4m3.e4m3.f16 "
                 "{%0,%1}, {%2,%3,%4,%5}, {%6,%7}, {%8,%8};"
                 : "=r"(c[0]), "=r"(c[1])
                 : "r"(a[0]), "r"(a[1]), "r"(a[2]), "r"(a[3]), "r"(b[0]), "r"(b[1]), "r"(0u));
}
__device__ __forceinline__ void copy_tile(uint32_t dstBase, const void* src, int tid) {
    #pragma unroll
    for (int jj = 0; jj < 4; ++jj) {
        int c = jj * 256 + tid;
        int row = c >> 3, col = c & 7;
        cpa16(dstBase + row * AS + col * 16, (const char*)src + row * 128 + col * 16);
    }
}
// B tile + its labels/M into a slot (0..2)
__device__ __forceinline__ void load_B(uint32_t sb, int slot, int tj,
                                       const int* labels, int tid) {
    copy_tile(sb + OFF_B + slot * TILE_SM, (const char*)g_f8 + tj * 128 * DIM, tid);
    if (tid < 32)       cpa16(sb + OFF_CLAB + slot * 512 + tid * 16, labels + tj * 128 + tid * 4);
    else if (tid < 64)  cpa16(sb + OFF_CM + slot * 512 + (tid - 32) * 16, g_M + tj * 128 + (tid - 32) * 4);
}

// ---------------- kernel 1: fp32 -> e4m3*sqrt2 (2-row ILP) + norms + zero accums ----------------
__global__ void convert_kernel(const float* __restrict__ emb) {
    const int idx = blockIdx.x * blockDim.x + threadIdx.x;   // 131072 threads
    const int lane = idx & 31;
    const int row0 = idx >> 5;                               // 0..4095
    const int row1 = row0 + (NROWS / 2);
    if (idx < 7) {                                           // zero finalize state
        if (idx < 3)      g_cnt[idx] = 0;
        else if (idx < 6) g_lsum[idx - 3] = 0.f;
        else              g_done = 0;
    }
    const float4* e4 = (const float4*)emb;
    const float s = 1.41421356237f;                          // folds 1/TEMPERATURE
    float4 v0 = e4[row0 * 32 + lane];                        // two independent chains
    float4 v1 = e4[row1 * 32 + lane];

    unsigned a0 = __nv_cvt_float_to_fp8(v0.x * s, __NV_SATFINITE, __NV_E4M3);
    unsigned a1 = __nv_cvt_float_to_fp8(v0.y * s, __NV_SATFINITE, __NV_E4M3);
    unsigned a2 = __nv_cvt_float_to_fp8(v0.z * s, __NV_SATFINITE, __NV_E4M3);
    unsigned a3 = __nv_cvt_float_to_fp8(v0.w * s, __NV_SATFINITE, __NV_E4M3);
    g_f8[row0 * 32 + lane] = a0 | (a1 << 8) | (a2 << 16) | (a3 << 24);
    unsigned b0 = __nv_cvt_float_to_fp8(v1.x * s, __NV_SATFINITE, __NV_E4M3);
    unsigned b1 = __nv_cvt_float_to_fp8(v1.y * s, __NV_SATFINITE, __NV_E4M3);
    unsigned b2 = __nv_cvt_float_to_fp8(v1.z * s, __NV_SATFINITE, __NV_E4M3);
    unsigned b3 = __nv_cvt_float_to_fp8(v1.w * s, __NV_SATFINITE, __NV_E4M3);
    g_f8[row1 * 32 + lane] = b0 | (b1 << 8) | (b2 << 16) | (b3 << 24);

    float n0 = v0.x * v0.x + v0.y * v0.y + v0.z * v0.z + v0.w * v0.w;
    float n1 = v1.x * v1.x + v1.y * v1.y + v1.z * v1.z + v1.w * v1.w;
    #pragma unroll
    for (int o = 16; o; o >>= 1) {
        n0 += __shfl_xor_sync(0xffffffffu, n0, o);
        n1 += __shfl_xor_sync(0xffffffffu, n1, o);
    }
    if (lane == 0) {
        g_M[row0] = 2.f * n0;     // row softmax reference (margin >= ~50)
        g_p[row0] = 0.f;
        g_n[row0] = 0.f;
        g_M[row1] = 2.f * n1;
        g_p[row1] = 0.f;
        g_n[row1] = 0.f;
    }
}

// ---------------- kernel 2: symmetric FP8 GEMM, triple-buffered B, one barrier/job ----------------
__global__ __launch_bounds__(256, 2)
void sim_mma_kernel(const int* __restrict__ labels) {
    extern __shared__ unsigned char smem[];
    const uint32_t sb = smem_u32(smem);
    const int tid = threadIdx.x, lane = tid & 31, wid = tid >> 5;
    const int warp_m = wid & 3, warp_n = wid >> 2;       // 4 x 2 warp grid

    // job range: 2080 = 296*7 + 8 -> first 8 CTAs take 8 jobs
    const int b = blockIdx.x;
    const int g0 = b * 7 + (b < 8 ? b : 8);
    const int njobs = 7 + (b < 8 ? 1 : 0);

    int ti = 0, rem = g0;
    while (rem >= N_TILES - ti) { rem -= N_TILES - ti; ++ti; }
    int tj = ti + rem;

    // prologue: A into parity slot, B/labels/M into slot 0
    copy_tile(sb + OFF_A0 + (ti & 1) * TILE_SM, (const char*)g_f8 + ti * 128 * DIM, tid);
    load_B(sb, 0, tj, labels, tid);
    asm volatile("cp.async.commit_group;");

    int bslot = 0;
    for (int k = 0; k < njobs; ++k) {
        // prefetch job k+1: B into next slot (read last in job k-2, safe per barrier k-1);
        // A only when row tile changes, into the opposite parity slot.
        int ni = ti, nj = tj + 1;
        if (nj == N_TILES) { ni = ti + 1; nj = ni; }
        int nslot = bslot + 1; if (nslot == 3) nslot = 0;
        if (k + 1 < njobs) {
            load_B(sb, nslot, nj, labels, tid);
            if (ni != ti)
                copy_tile(sb + OFF_A0 + (ni & 1) * TILE_SM,
                          (const char*)g_f8 + ni * 128 * DIM, tid);
        }
        asm volatile("cp.async.commit_group;");
        asm volatile("cp.async.wait_group 1;");          // job k resident (this thread)
        __syncthreads();                                 // single barrier: publish job k

        // per-thread row info (L2-hot LDG)
        int rowG[4], myLab[4];
        float Mref[4];
        #pragma unroll
        for (int s = 0; s < 4; ++s) {
            rowG[s]  = ti * 128 + warp_m * 32 + (s >> 1) * 16 + (s & 1) * 8 + (lane >> 2);
            myLab[s] = labels[rowG[s]];
            Mref[s]  = g_M[rowG[s]];
        }

        // A fragments
        uint32_t af[2][4][4];
        {
            const uint32_t abase = sb + OFF_A0 + (ti & 1) * TILE_SM;
            const int arow = warp_m * 32 + (lane & 15);
            #pragma unroll
            for (int mt = 0; mt < 2; ++mt)
                #pragma unroll
                for (int ks = 0; ks < 4; ++ks)
                    ldsm4(af[mt][ks], abase + (arow + mt * 16) * AS + ks * 32 + (lane >> 4) * 16);
        }

        // ---- GEMM: 32x64 per warp, f16 accumulators ----
        uint32_t acc[2][8][2];
        const uint32_t bbase = sb + OFF_B + bslot * TILE_SM;
        #pragma unroll
        for (int ks = 0; ks < 4; ++ks) {
            uint32_t bfr[8][2];
            #pragma unroll
            for (int np = 0; np < 4; ++np) {
                uint32_t r[4];
                uint32_t addr = bbase
                    + (warp_n * 64 + np * 16 + ((lane >> 4) & 1) * 8 + (lane & 7)) * AS
                    + ks * 32 + ((lane >> 3) & 1) * 16;
                ldsm4(r, addr);
                bfr[np * 2][0] = r[0]; bfr[np * 2][1] = r[1];
                bfr[np * 2 + 1][0] = r[2]; bfr[np * 2 + 1][1] = r[3];
            }
            #pragma unroll
            for (int mt = 0; mt < 2; ++mt)
                #pragma unroll
                for (int nt = 0; nt < 8; ++nt) {
                    if (ks == 0) mma16832h_z(acc[mt][nt], af[mt][0], bfr[nt]);
                    else         mma16832h(acc[mt][nt], af[mt][ks], bfr[nt]);
                }
        }

        const int* clab = (const int*)(smem + OFF_CLAB) + bslot * 128;
        const float* cm = (const float*)(smem + OFF_CM) + bslot * 128;
        const int colBase = tj * 128;

        // per-thread column guard threshold
        float minM = FLT_MAX;
        #pragma unroll
        for (int nt = 0; nt < 8; ++nt) {
            minM = fminf(minM, cm[warp_n * 64 + nt * 8 + (lane & 3) * 2]);
            minM = fminf(minM, cm[warp_n * 64 + nt * 8 + (lane & 3) * 2 + 1]);
        }

        // ---- row-side epilogue: packed-half max scan + rare slow path ----
        float smaxf[4];
        float ps[4] = {0.f,0.f,0.f,0.f}, ns[4] = {0.f,0.f,0.f,0.f};
        #pragma unroll
        for (int s = 0; s < 4; ++s) {
            const int mt = s >> 1, rh = s & 1;
            __half2 m2 = *(const __half2*)&acc[mt][0][rh];
            #pragma unroll
            for (int nt = 1; nt < 8; ++nt)
                m2 = __hmax2(m2, *(const __half2*)&acc[mt][nt][rh]);
            smaxf[s] = __half2float(__hmax(__low2half(m2), __high2half(m2)));
            if (smaxf[s] > Mref[s] - 87.f) {             // rare (diagonal tiles)
                const int rg = rowG[s], li = myLab[s];
                #pragma unroll
                for (int nt = 0; nt < 8; ++nt) {
                    float2 f2 = __half22float2(*(const __half2*)&acc[mt][nt][rh]);
                    #pragma unroll
                    for (int c = 0; c < 2; ++c) {
                        float x = (c ? f2.y : f2.x) - Mref[s];
                        if (x > -87.f) {
                            int ci = warp_n * 64 + nt * 8 + (lane & 3) * 2 + c;
                            if (colBase + ci != rg) {
                                float e = __expf(x);
                                int lj = clab[ci];
                                bool pos = (li == 0) | (lj == li) | (lj == 0);
                                if (pos) ps[s] += e; else ns[s] += e;
                            }
                        }
                    }
                }
            }
        }
        float any = ps[0]+ps[1]+ps[2]+ps[3]+ns[0]+ns[1]+ns[2]+ns[3];
        if (__any_sync(0xffffffffu, any != 0.f)) {
            #pragma unroll
            for (int s = 0; s < 4; ++s) {
                ps[s] += __shfl_xor_sync(0xffffffffu, ps[s], 1);
                ps[s] += __shfl_xor_sync(0xffffffffu, ps[s], 2);
                ns[s] += __shfl_xor_sync(0xffffffffu, ns[s], 1);
                ns[s] += __shfl_xor_sync(0xffffffffu, ns[s], 2);
                if ((lane & 3) == 0) {
                    if (ps[s] != 0.f) atomicAdd(&g_p[rowG[s]], ps[s]);
                    if (ns[s] != 0.f) atomicAdd(&g_n[rowG[s]], ns[s]);
                }
            }
        }

        // ---- col-side epilogue (off-diagonal jobs only) ----
        if (ti != tj) {
            float tmax = fmaxf(fmaxf(smaxf[0], smaxf[1]), fmaxf(smaxf[2], smaxf[3]));
            if (tmax > minM - 87.f) {                    // essentially never
                #pragma unroll
                for (int s = 0; s < 4; ++s) {
                    const int mt = s >> 1, rh = s & 1;
                    const int li = myLab[s];
                    #pragma unroll
                    for (int nt = 0; nt < 8; ++nt) {
                        float2 f2 = __half22float2(*(const __half2*)&acc[mt][nt][rh]);
                        #pragma unroll
                        for (int c = 0; c < 2; ++c) {
                            int ci = warp_n * 64 + nt * 8 + (lane & 3) * 2 + c;
                            float x = (c ? f2.y : f2.x) - cm[ci];
                            if (x > -87.f) {
                                float e = __expf(x);
                                int lj = clab[ci];
                                bool pos = (li == 0) | (lj == li) | (lj == 0);
                                if (pos) atomicAdd(&g_p[colBase + ci], e);
                                else     atomicAdd(&g_n[colBase + ci], e);
                            }
                        }
                    }
                }
            }
        }

        ti = ni; tj = nj; bslot = nslot;
    }
}

// ---------------- kernel 3: finalize via warp shfl reductions ----------------
__global__ void finalize_kernel(const int* __restrict__ labels, float* __restrict__ out) {
    const int tid = threadIdx.x, lane = tid & 31;
    const int r = blockIdx.x * 256 + tid;
    const int li = labels[r];
    const float P = g_p[r], Ng = g_n[r];
    const float loss = -logf((P + EPSL) / (P + Ng + EPSL));

    float s0 = (li == -1) ? loss : 0.f;
    float s1 = (li ==  0) ? loss : 0.f;
    float s2 = (li ==  1) ? loss : 0.f;
    unsigned bm = __ballot_sync(0xffffffffu, li == -1);
    unsigned bz = __ballot_sync(0xffffffffu, li ==  0);
    unsigned bp = __ballot_sync(0xffffffffu, li ==  1);
    #pragma unroll
    for (int o = 16; o; o >>= 1) {
        s0 += __shfl_xor_sync(0xffffffffu, s0, o);
        s1 += __shfl_xor_sync(0xffffffffu, s1, o);
        s2 += __shfl_xor_sync(0xffffffffu, s2, o);
    }
    if (lane == 0) {
        atomicAdd(&g_lsum[0], s0);
        atomicAdd(&g_lsum[1], s1);
        atomicAdd(&g_lsum[2], s2);
        atomicAdd(&g_cnt[0], (int)__popc(bm));
        atomicAdd(&g_cnt[1], (int)__popc(bz));
        atomicAdd(&g_cnt[2], (int)__popc(bp));
    }
    __threadfence();
    __syncthreads();

    if (tid == 0) {
        int ticket = atomicAdd(&g_done, 1);
        if (ticket == gridDim.x - 1) {                   // last block finishing
            int cm = g_cnt[0], c0 = g_cnt[1], cp = g_cnt[2];
            float total = 0.f, count = 0.f;
            if (cm - 1 + c0 > 0) { total += g_lsum[0]; count += (float)cm; }
            { total += g_lsum[1]; count += (float)c0; } // label 0: NROWS-1 > 0 always
            if (cp - 1 + c0 > 0) { total += g_lsum[2]; count += (float)cp; }
            out[0] = (count > 0.f) ? (total / fmaxf(count, 1.f)) : 0.f;
        }
    }
}

extern "C" void kernel_launch(void* const* d_in, const int* in_sizes, int n_in,
                              void* d_out, int out_size) {
    const int*   labels = (const int*)d_in[0];
    const float* emb    = (const float*)d_in[1];
    float*       out    = (float*)d_out;

    cudaFuncSetAttribute(sim_mma_kernel,
                         cudaFuncAttributeMaxDynamicSharedMemorySize, SMEM_BYTES);

    convert_kernel<<<NROWS * 32 / 2 / 256, 256>>>(emb);
    sim_mma_kernel<<<NCTA, 256, SMEM_BYTES>>>(labels);
    finalize_kernel<<<NROWS / 256, 256>>>(labels, out);
}